// round 10
// baseline (speedup 1.0000x reference)
#include <cuda_runtime.h>
#include <math.h>
#include <stdint.h>

#define Bn 256
#define Tn 512
#define Fn 16
#define Hn 256
#define Gn (4*Hn)        // 1024 gate cols (interleaved unit*4+gate)
#define CLSZ 4           // CTAs per cluster (unit-split)
#define BT 8             // batches per cluster group
#define NGRP (Bn/BT)     // 32 groups
#define UPC (Hn/CLSZ)    // 64 units per CTA
#define SSZ 16           // k-rows per cp.async stage
#define NBUF 3           // stage ring depth
#define NTHR 512         // threads per CTA (two k-halves)

typedef unsigned long long u64;

// ---- scratch (__device__ globals; no allocation allowed) ----
__device__ float g_Wc0[(Fn+Hn)*Gn];   // [k][unit*4+gate] interleaved, layer 0
__device__ float g_Wc1[(Hn+Hn)*Gn];   // layer 1
__device__ float g_b0[Gn], g_b1[Gn];  // interleaved combined biases
__device__ float g_h0out[(size_t)Bn*Tn*Hn];  // layer-0 hidden sequence [b][t][u]
__device__ float g_hlast[Bn*Hn];             // layer-1 h at t = len-1

// ---------------- helpers ----------------
__device__ __forceinline__ u64 pack2(float a, float b) {
    u64 r; asm("mov.b64 %0, {%1, %2};" : "=l"(r) : "f"(a), "f"(b)); return r;
}
__device__ __forceinline__ void unpack2(u64 v, float& a, float& b) {
    asm("mov.b64 {%0, %1}, %2;" : "=f"(a), "=f"(b) : "l"(v));
}
__device__ __forceinline__ void ffma2(u64& acc, u64 a, u64 b) {
    asm("fma.rn.f32x2 %0, %1, %2, %0;" : "+l"(acc) : "l"(a), "l"(b));
}
__device__ __forceinline__ void fadd2(u64& acc, u64 a) {
    asm("add.rn.f32x2 %0, %0, %1;" : "+l"(acc) : "l"(a));
}
__device__ __forceinline__ float fast_sigmoid(float x) {
    return 1.f / (1.f + __expf(-x));
}
__device__ __forceinline__ float fast_tanh(float x) {
    return 1.f - 2.f / (1.f + __expf(2.f * x));
}
__device__ __forceinline__ uint32_t ctarank() {
    uint32_t r; asm("mov.u32 %0, %%cluster_ctarank;" : "=r"(r)); return r;
}
__device__ __forceinline__ void cluster_sync() {
    asm volatile("barrier.cluster.arrive.aligned;" ::: "memory");
    asm volatile("barrier.cluster.wait.aligned;"   ::: "memory");
}
__device__ __forceinline__ void st_cluster_u64(uint32_t laddr, uint32_t rank, u64 v) {
    asm volatile(
        "{ .reg .b32 ra;\n\t"
        "  mapa.shared::cluster.u32 ra, %0, %1;\n\t"
        "  st.shared::cluster.u64 [ra], %2; }"
        :: "r"(laddr), "r"(rank), "l"(v) : "memory");
}
__device__ __forceinline__ void cp16(uint32_t dst_smem, const void* src) {
    asm volatile("cp.async.cg.shared.global [%0], [%1], 16;"
                 :: "r"(dst_smem), "l"(src) : "memory");
}
__device__ __forceinline__ void cp_commit() {
    asm volatile("cp.async.commit_group;" ::: "memory");
}
template<int N> __device__ __forceinline__ void cp_wait() {
    asm volatile("cp.async.wait_group %0;" :: "n"(N) : "memory");
}

// ---------------- weight prep: transpose + interleave [k][u*4+g] ----------------
__global__ void prep_kernel(const float* __restrict__ wih0, const float* __restrict__ whh0,
                            const float* __restrict__ bih0, const float* __restrict__ bhh0,
                            const float* __restrict__ wih1, const float* __restrict__ whh1,
                            const float* __restrict__ bih1, const float* __restrict__ bhh1) {
    int idx = blockIdx.x * blockDim.x + threadIdx.x;
    int stride = gridDim.x * blockDim.x;
    const int n0 = (Fn+Hn)*Gn, n1 = (Hn+Hn)*Gn;
    for (int i = idx; i < n0; i += stride) {
        int k = i >> 10, col = i & 1023, u = col >> 2, g = col & 3;
        int jo = g*Hn + u;
        g_Wc0[i] = (k < Fn) ? wih0[jo*Fn + k] : whh0[jo*Hn + (k - Fn)];
    }
    for (int i = idx; i < n1; i += stride) {
        int k = i >> 10, col = i & 1023, u = col >> 2, g = col & 3;
        int jo = g*Hn + u;
        g_Wc1[i] = (k < Hn) ? wih1[jo*Hn + k] : whh1[jo*Hn + (k - Hn)];
    }
    for (int col = idx; col < Gn; col += stride) {
        int u = col >> 2, g = col & 3, jo = g*Hn + u;
        g_b0[col] = bih0[jo] + bhh0[jo];
        g_b1[col] = bih1[jo] + bhh1[jo];
    }
}

// ---------------- clustered LSTM layer, 512 thr, k-split + DSMEM h-exchange ----
// 128 CTAs, cluster of 4; group (blockIdx/4) owns 8 batches; rank owns 64 units.
// half = tid>>8 processes its k-half; r=tid&255: u=r>>2 (local unit), q=r&3 (pair).
// v buffer layout (u64 rows x BT): [ x(XDIM) | h parity0 (Hn) | h parity1 (Hn) ].
// Update threads (half 0) push h into all 4 CTAs' v[par^1] via st.shared::cluster;
// one cluster.sync per step publishes it. Weights stream via per-half cp.async rings.
template<int KIN, int XDIM, int LAYER>
__global__ __launch_bounds__(NTHR, 1) __cluster_dims__(CLSZ, 1, 1)
void lstm_layer(const float* __restrict__ xin, const int* __restrict__ lengths)
{
    constexpr int KH0   = ((KIN/2 + SSZ - 1)/SSZ)*SSZ;   // half-0 k count (SSZ-mult)
    constexpr int V2SZ  = (XDIM + 2*Hn)*BT*8;            // bytes
    constexpr int WRHALF= NBUF*SSZ*256;                  // floats per half ring

    extern __shared__ __align__(16) char smem[];
    u64*   v2  = reinterpret_cast<u64*>(smem);
    float* wst = reinterpret_cast<float*>(smem + V2SZ);
    u64*   red = reinterpret_cast<u64*>(smem + V2SZ + 2*WRHALF*4);  // [256][4]
    __shared__ int len_sh[BT];

    const float* __restrict__ Wc   = LAYER ? g_Wc1 : g_Wc0;
    const float* __restrict__ bias = LAYER ? g_b1 : g_b0;

    const int tid  = threadIdx.x;
    const int half = tid >> 8;
    const int r    = tid & 255;
    const int u    = r >> 2;            // local unit 0..63
    const int q    = r & 3;             // batch pair 0..3
    const int wid8 = r >> 5, lane = tid & 31;
    const int grp  = blockIdx.x >> 2;
    const uint32_t rank = ctarank();
    const int b0g  = grp * BT;
    const int unit = (int)rank * UPC + u;
    const int kbeg = half ? KH0 : 0;
    const int nst  = half ? (KIN - KH0)/SSZ : KH0/SSZ;

    const u64 bias01 = *reinterpret_cast<const u64*>(bias + unit*4);
    const u64 bias23 = *reinterpret_cast<const u64*>(bias + unit*4 + 2);

    if (tid < BT) len_sh[tid] = lengths[b0g + tid];

    // zero both h parity regions
    for (int i = tid; i < 2*Hn*BT; i += NTHR) v2[(size_t)XDIM*BT + i] = 0ull;
    // x for t = 0
    if (XDIM == Fn) {
        if (tid < Fn*BT) {
            int k = tid >> 3, b = tid & 7;
            float xv = xin[((size_t)(b0g + b) * Tn + 0) * Fn + k];
            v2[k*BT + b] = pack2(xv, xv);
        }
    } else {
        int k = tid >> 1, bq = tid & 1;
        const float* src = g_h0out + ((size_t)(b0g + bq*4) * Tn + 0) * Hn + k;
        #pragma unroll
        for (int j = 0; j < 4; ++j) {
            float hv = src[(size_t)j * Tn * Hn];
            v2[k*BT + bq*4 + j] = pack2(hv, hv);
        }
    }
    __syncthreads();

    float c0 = 0.f, c1 = 0.f;
    const uint32_t wst_s = (uint32_t)__cvta_generic_to_shared(wst)
                           + (uint32_t)half * (WRHALF*4);
    const uint32_t v2_s  = (uint32_t)__cvta_generic_to_shared(v2);
    const float* wloc = wst + half*WRHALF;
    int par = 0;

    for (int t = 0; t < Tn; ++t) {
        // ---- issue stages 0,1 of this half's k range ----
        #pragma unroll
        for (int s0 = 0; s0 < 2; ++s0) {
            #pragma unroll
            for (int j = 0; j < 4; ++j) {
                int c = lane + 32*j, kl = c >> 3, ci = c & 7;
                const float* src = Wc + (size_t)(kbeg + s0*SSZ + kl) * Gn
                                   + rank*256 + wid8*32 + ci*4;
                cp16(wst_s + ((s0 % NBUF)*SSZ + kl)*1024 + wid8*128 + ci*16, src);
            }
            cp_commit();
        }

        u64 a01_0 = half ? 0ull : bias01, a23_0 = half ? 0ull : bias23;
        u64 a01_1 = half ? 0ull : bias01, a23_1 = half ? 0ull : bias23;

        for (int s = 0; s < nst; ++s) {
            if (s + 2 < nst) {
                #pragma unroll
                for (int j = 0; j < 4; ++j) {
                    int c = lane + 32*j, kl = c >> 3, ci = c & 7;
                    const float* src = Wc + (size_t)(kbeg + (s+2)*SSZ + kl) * Gn
                                       + rank*256 + wid8*32 + ci*4;
                    cp16(wst_s + (((s+2) % NBUF)*SSZ + kl)*1024 + wid8*128 + ci*16, src);
                }
                cp_commit();
                cp_wait<2>();
            } else if (s + 1 < nst) {
                cp_wait<1>();
            } else {
                cp_wait<0>();
            }
            __syncwarp();

            const int ak = kbeg + s*SSZ;
            const u64* vst = v2 + ((size_t)ak + (ak >= XDIM ? (size_t)par*Hn : 0))*BT + q*2;
            const float* wb = wloc + (s % NBUF)*(SSZ*256) + u*4;
            #pragma unroll
            for (int kl = 0; kl < SSZ; ++kl) {
                const ulonglong2 w = *reinterpret_cast<const ulonglong2*>(wb + kl*256);
                const ulonglong2 p = *reinterpret_cast<const ulonglong2*>(vst + kl*BT);
                ffma2(a01_0, w.x, p.x); ffma2(a23_0, w.y, p.x);
                ffma2(a01_1, w.x, p.y); ffma2(a23_1, w.y, p.y);
            }
        }

        // ---- cross-half reduction ----
        if (half) {
            ulonglong2* rd = reinterpret_cast<ulonglong2*>(red + r*4);
            rd[0] = make_ulonglong2(a01_0, a23_0);
            rd[1] = make_ulonglong2(a01_1, a23_1);
        }
        __syncthreads();

        if (half == 0) {
            const ulonglong2* rd = reinterpret_cast<const ulonglong2*>(red + r*4);
            ulonglong2 r0 = rd[0], r1 = rd[1];
            fadd2(a01_0, r0.x); fadd2(a23_0, r0.y);
            fadd2(a01_1, r1.x); fadd2(a23_1, r1.y);

            // ---- update (gate order i,f,g,o) ----
            float ig, fg, gg, og, h0v, h1v;
            unpack2(a01_0, ig, fg); unpack2(a23_0, gg, og);
            c0 = fast_sigmoid(fg) * c0 + fast_sigmoid(ig) * fast_tanh(gg);
            h0v = fast_sigmoid(og) * fast_tanh(c0);
            unpack2(a01_1, ig, fg); unpack2(a23_1, gg, og);
            c1 = fast_sigmoid(fg) * c1 + fast_sigmoid(ig) * fast_tanh(gg);
            h1v = fast_sigmoid(og) * fast_tanh(c1);

            // ---- DSMEM broadcast of h into every CTA's v[par^1] ----
            uint32_t dst = v2_s + (uint32_t)(((XDIM + (par^1)*Hn + unit)*BT + q*2) * 8);
            u64 hx0 = pack2(h0v, h0v), hx1 = pack2(h1v, h1v);
            #pragma unroll
            for (uint32_t rk = 0; rk < CLSZ; ++rk) {
                st_cluster_u64(dst,     rk, hx0);
                st_cluster_u64(dst + 8, rk, hx1);
            }

            if (LAYER == 0) {
                g_h0out[((size_t)(b0g + 2*q)   * Tn + t) * Hn + unit] = h0v;
                g_h0out[((size_t)(b0g + 2*q+1) * Tn + t) * Hn + unit] = h1v;
            } else {
                if (t == len_sh[2*q]   - 1) g_hlast[(b0g + 2*q)  *Hn + unit] = h0v;
                if (t == len_sh[2*q+1] - 1) g_hlast[(b0g + 2*q+1)*Hn + unit] = h1v;
            }
        }

        // ---- publish h to whole cluster (release/acquire) ----
        cluster_sync();

        // ---- prefetch x_{t+1} ----
        if (t + 1 < Tn) {
            if (XDIM == Fn) {
                if (tid < Fn*BT) {
                    int k = tid >> 3, b = tid & 7;
                    float xv = xin[((size_t)(b0g + b) * Tn + (t+1)) * Fn + k];
                    v2[k*BT + b] = pack2(xv, xv);
                }
            } else {
                int k = tid >> 1, bq = tid & 1;
                const float* src = g_h0out + ((size_t)(b0g + bq*4) * Tn + (t+1)) * Hn + k;
                #pragma unroll
                for (int j = 0; j < 4; ++j) {
                    float hv = src[(size_t)j * Tn * Hn];
                    v2[k*BT + bq*4 + j] = pack2(hv, hv);
                }
            }
        }
        __syncthreads();
        par ^= 1;
    }
}

// ---------------- final: relu(hlast) @ fc_w^T + fc_b ----------------
__global__ void final_kernel(const float* __restrict__ fc_w, const float* __restrict__ fc_b,
                             float* __restrict__ out) {
    __shared__ float red[256];
    int b = blockIdx.x, u = threadIdx.x;
    float v = fmaxf(g_hlast[b * Hn + u], 0.f) * fc_w[u];
    red[u] = v;
    __syncthreads();
    #pragma unroll
    for (int s = 128; s > 0; s >>= 1) {
        if (u < s) red[u] += red[u + s];
        __syncthreads();
    }
    if (u == 0) out[b] = red[0] + fc_b[0];
}

extern "C" void kernel_launch(void* const* d_in, const int* in_sizes, int n_in,
                              void* d_out, int out_size) {
    const float* x    = (const float*)d_in[0];
    const int*   lens = (const int*)  d_in[1];
    const float* wih0 = (const float*)d_in[2];
    const float* whh0 = (const float*)d_in[3];
    const float* bih0 = (const float*)d_in[4];
    const float* bhh0 = (const float*)d_in[5];
    const float* wih1 = (const float*)d_in[6];
    const float* whh1 = (const float*)d_in[7];
    const float* bih1 = (const float*)d_in[8];
    const float* bhh1 = (const float*)d_in[9];
    const float* fcw  = (const float*)d_in[10];
    const float* fcb  = (const float*)d_in[11];
    float* out = (float*)d_out;

    const int wring = 2 * NBUF*SSZ*256 * 4;                  // 98304 B
    const int smem0 = (Fn+2*Hn)*BT*8 + wring + 256*4*8;      // v2 + rings + red
    const int smem1 = (Hn+2*Hn)*BT*8 + wring + 256*4*8;
    cudaFuncSetAttribute(lstm_layer<Fn+Hn, Fn, 0>,
                         cudaFuncAttributeMaxDynamicSharedMemorySize, smem0);
    cudaFuncSetAttribute(lstm_layer<Hn+Hn, Hn, 1>,
                         cudaFuncAttributeMaxDynamicSharedMemorySize, smem1);

    prep_kernel<<<148, 256>>>(wih0, whh0, bih0, bhh0, wih1, whh1, bih1, bhh1);
    lstm_layer<Fn+Hn, Fn, 0><<<NGRP*CLSZ, NTHR, smem0>>>(x, lens);
    lstm_layer<Hn+Hn, Hn, 1><<<NGRP*CLSZ, NTHR, smem1>>>(nullptr, lens);
    final_kernel<<<Bn, 256>>>(fcw, fcb, out);
}